// round 7
// baseline (speedup 1.0000x reference)
#include <cuda_runtime.h>
#include <math.h>

#define BB   128
#define NNOD 50
#define SEQ  51
#define DIM  128
#define NH   8
#define DHE  16
#define FFD  512
#define NLE  6
#define NLD  2
#define MTOT (BB*SEQ)            // 6528
#define SZ_MD (MTOT*DIM)         // 835584

// ---------------- scratch ----------------
#define OFF_T    (SZ_MD)
#define OFF_Q    (2*SZ_MD)
#define OFF_O    (5*SZ_MD)
#define OFF_F    (6*SZ_MD)
#define OFF_KATT (10*SZ_MD)
#define OFF_VATT (12*SZ_MD)
#define OFF_KFIN (14*SZ_MD)
#define OFF_PART (15*SZ_MD)
#define OFF_MEAN (OFF_PART + 16384)
#define OFF_RSTD (OFF_MEAN + 128)
#define OFF_PE   (OFF_RSTD + 128)
#define OFF_KC   (OFF_PE + NNOD*DIM)
#define SZ_KC    (NLD*BB*NH*NNOD*DHE)
#define OFF_VC   (OFF_KC + SZ_KC)
#define SCRATCH_TOTAL (OFF_VC + SZ_KC)

__device__ float g_scratch[SCRATCH_TOTAL];

// ---------------- embedding ----------------
__global__ void embed_kernel(const float* __restrict__ x,
                             const float* __restrict__ w_in,
                             const float* __restrict__ b_in,
                             const float* __restrict__ start_ph,
                             float* __restrict__ h)
{
    int i = blockIdx.x * blockDim.x + threadIdx.x;
    if (i >= MTOT * DIM) return;
    int d = i & 127;
    int row = i >> 7;
    int s = row % SEQ;
    int b = row / SEQ;
    float v;
    if (s < NNOD) {
        const float* xp = x + (b * NNOD + s) * 2;
        v = xp[0] * w_in[d] + xp[1] * w_in[DIM + d] + b_in[d];
    } else {
        v = start_ph[d];
    }
    h[i] = v;
}

// ---------------- positional encoding ----------------
__global__ void pe_kernel(float* __restrict__ pe)
{
    int i = blockIdx.x * blockDim.x + threadIdx.x;
    if (i >= NNOD * DIM) return;
    int t = i >> 7, d = i & 127;
    double e = (double)(2 * (d / 2)) / 128.0;
    double ang = (double)t * pow(10000.0, -e);
    pe[i] = (float)(((d & 1) == 0) ? sin(ang) : cos(ang));
}

// ---------------- SGEMM ----------------
template<bool BIAS, bool RELU, bool RES, bool ZSTRIDE>
__global__ void __launch_bounds__(256) sgemm(const float* __restrict__ A,
                                             const float* __restrict__ W,
                                             const float* __restrict__ bias,
                                             const float* __restrict__ R,
                                             float* __restrict__ C,
                                             int M, int N, int K)
{
    if (ZSTRIDE) {
        int z = blockIdx.z;
        W += (size_t)z * K * N;
        if (BIAS) bias += (size_t)z * N;
        C += (size_t)z * M * N;
    }
    __shared__ float As[16][68];
    __shared__ float Bs[16][68];
    int bm = blockIdx.y * 64, bn = blockIdx.x * 64;
    int tid = threadIdx.x;
    int tr = tid >> 4, tc = tid & 15;
    float acc[4][4] = {};
    for (int k0 = 0; k0 < K; k0 += 16) {
        int m = tid >> 2, kk = (tid & 3) * 4;
        float4 av = *(const float4*)&A[(bm + m) * K + k0 + kk];
        As[kk + 0][m] = av.x; As[kk + 1][m] = av.y;
        As[kk + 2][m] = av.z; As[kk + 3][m] = av.w;
        int kr = tid >> 4, cc = (tid & 15) * 4;
        float4 bv = *(const float4*)&W[(k0 + kr) * N + bn + cc];
        Bs[kr][cc + 0] = bv.x; Bs[kr][cc + 1] = bv.y;
        Bs[kr][cc + 2] = bv.z; Bs[kr][cc + 3] = bv.w;
        __syncthreads();
#pragma unroll
        for (int k2 = 0; k2 < 16; k2++) {
            float ra[4], rb[4];
#pragma unroll
            for (int i = 0; i < 4; i++) { ra[i] = As[k2][tr * 4 + i]; rb[i] = Bs[k2][tc * 4 + i]; }
#pragma unroll
            for (int i = 0; i < 4; i++)
#pragma unroll
                for (int j = 0; j < 4; j++) acc[i][j] += ra[i] * rb[j];
        }
        __syncthreads();
    }
#pragma unroll
    for (int i = 0; i < 4; i++) {
        int m = bm + tr * 4 + i;
#pragma unroll
        for (int j = 0; j < 4; j++) {
            int n = bn + tc * 4 + j;
            float v = acc[i][j];
            if (BIAS) v += bias[n];
            if (RELU) v = fmaxf(v, 0.f);
            if (RES)  v += R[m * N + n];
            C[m * N + n] = v;
        }
    }
}

// ---------------- encoder attention ----------------
__global__ void __launch_bounds__(128) enc_attn(const float* __restrict__ Q,
                                                const float* __restrict__ K,
                                                const float* __restrict__ V,
                                                float* __restrict__ O)
{
    __shared__ float Qs[SEQ][DHE], Ks[SEQ][DHE], Vs[SEQ][DHE];
    __shared__ float P[SEQ][SEQ + 1];
    int bh = blockIdx.x;
    int b = bh / NH, hh = bh % NH;
    int tid = threadIdx.x;
    for (int i = tid; i < SEQ * DHE; i += 128) {
        int s = i / DHE, j = i % DHE;
        int g = (b * SEQ + s) * DIM + hh * DHE + j;
        Qs[s][j] = Q[g]; Ks[s][j] = K[g]; Vs[s][j] = V[g];
    }
    __syncthreads();
    for (int p = tid; p < SEQ * SEQ; p += 128) {
        int q = p / SEQ, k = p % SEQ;
        float s = 0.f;
#pragma unroll
        for (int j = 0; j < DHE; j++) s += Qs[q][j] * Ks[k][j];
        P[q][k] = s * 0.25f;
    }
    __syncthreads();
    if (tid < SEQ) {
        float mx = -1e30f;
        for (int k = 0; k < SEQ; k++) mx = fmaxf(mx, P[tid][k]);
        float sum = 0.f;
        for (int k = 0; k < SEQ; k++) { float e = expf(P[tid][k] - mx); P[tid][k] = e; sum += e; }
        float inv = 1.f / sum;
        for (int k = 0; k < SEQ; k++) P[tid][k] *= inv;
    }
    __syncthreads();
    for (int p = tid; p < SEQ * DHE; p += 128) {
        int q = p / DHE, j = p % DHE;
        float s = 0.f;
        for (int k = 0; k < SEQ; k++) s += P[q][k] * Vs[k][j];
        O[(b * SEQ + q) * DIM + hh * DHE + j] = s;
    }
}

// ---------------- BatchNorm (deterministic 3-stage) ----------------
__global__ void __launch_bounds__(256) bn_partial(const float* __restrict__ X,
                                                  float* __restrict__ part)
{
    int d = threadIdx.x & 127, half = threadIdx.x >> 7;
    int r0 = blockIdx.x * 102;
    float s = 0.f, ss = 0.f;
    for (int r = r0 + half; r < r0 + 102; r += 2) {
        float v = X[r * DIM + d];
        s += v; ss += v * v;
    }
    __shared__ float sh[2][2][128];
    sh[half][0][d] = s; sh[half][1][d] = ss;
    __syncthreads();
    if (!half) {
        part[blockIdx.x * 256 + d]       = s + sh[1][0][d];
        part[blockIdx.x * 256 + 128 + d] = ss + sh[1][1][d];
    }
}

__global__ void bn_reduce(const float* __restrict__ part,
                          float* __restrict__ mean, float* __restrict__ rstd)
{
    int d = threadIdx.x;
    float s = 0.f, ss = 0.f;
    for (int b = 0; b < 64; b++) { s += part[b * 256 + d]; ss += part[b * 256 + 128 + d]; }
    float m = s * (1.f / (float)MTOT);
    float v = ss * (1.f / (float)MTOT) - m * m;
    mean[d] = m;
    rstd[d] = rsqrtf(v + 1e-5f);
}

__global__ void __launch_bounds__(256) bn_apply(const float* __restrict__ X,
                                                const float* __restrict__ mean,
                                                const float* __restrict__ rstd,
                                                const float* __restrict__ gamma,
                                                const float* __restrict__ beta,
                                                float* __restrict__ Y)
{
    int i = blockIdx.x * blockDim.x + threadIdx.x;
    if (i >= MTOT * DIM) return;
    int d = i & 127;
    Y[i] = gamma[d] * (X[i] - mean[d]) * rstd[d] + beta[d];
}

// ---------------- decoder: dual-element float4 GEMV partial ----------------
// k-range [k0, k0+NK), columns 4c..4c+3, both elements share each weight load.
template<int NK>
__device__ __forceinline__ void gemv4_dual(const float* __restrict__ x0,
                                           const float* __restrict__ x1,
                                           const float* __restrict__ W,
                                           int c, int k0,
                                           float* a0, float* a1)
{
    const float4* Wp = (const float4*)(W + k0 * DIM) + c;
    const float* xp0 = x0 + k0;
    const float* xp1 = x1 + k0;
#pragma unroll
    for (int k = 0; k < NK; k++) {
        float4 w = Wp[k * 32];
        float v0 = xp0[k], v1 = xp1[k];
        a0[0] += v0 * w.x; a0[1] += v0 * w.y; a0[2] += v0 * w.z; a0[3] += v0 * w.w;
        a1[0] += v1 * w.x; a1[1] += v1 * w.y; a1[2] += v1 * w.z; a1[3] += v1 * w.w;
    }
}

// ---------------- persistent decoder: 2 batch elements per block, 512 threads ----------------
__global__ void __launch_bounds__(512) decoder_kernel(
    const float* __restrict__ h_enc, const float* __restrict__ pe,
    const float* __restrict__ Katt, const float* __restrict__ Vatt,
    const float* __restrict__ Kfin,
    float* __restrict__ Kc, float* __restrict__ Vc,
    const float* __restrict__ dsw, const float* __restrict__ dsb,
    const float* __restrict__ dcw, const float* __restrict__ dcb,
    const float* __restrict__ dw1, const float* __restrict__ db1,
    const float* __restrict__ dw2, const float* __restrict__ db2,
    const float* __restrict__ dln, const float* __restrict__ wqf,
    float* __restrict__ out)
{
    int tid = threadIdx.x;
    int b0 = blockIdx.x * 2;
    int c = tid & 31;            // col-group (cols 4c..4c+3) for 128-wide GEMVs
    int q16 = tid >> 5;          // 16-way k-group

    __shared__ float ht[2][DIM], sq[2][DIM], so[2][DIM], su[2][DIM];
    __shared__ float sf[2][FFD];
    __shared__ float pb[4096];               // shared partial buffer (16KB)
    __shared__ float sc[2][NH][SEQ + 1];
    __shared__ float red[16];
    __shared__ float slg[2][SEQ];
    __shared__ int   smask[2][SEQ];
    __shared__ int   scur[2];
    __shared__ float sslp[2];

    for (int p = tid; p < 2 * SEQ; p += 512) {
        int el = p / SEQ, n = p % SEQ;
        smask[el][n] = (n == NNOD) ? 1 : 0;
    }
    if (tid < 2) { scur[tid] = NNOD; sslp[tid] = 0.f; }
    __syncthreads();

    for (int t = 0; t < NNOD; t++) {
        if (tid < 256) {
            int el = tid >> 7, d = tid & 127;
            ht[el][d] = h_enc[((b0 + el) * SEQ + scur[el]) * DIM + d] + pe[t * DIM + d];
        }
        __syncthreads();

        for (int l = 0; l < NLD; l++) {
            const float* W  = dsw + l * 4 * DIM * DIM;
            const float* bb = dsb + l * 4 * DIM;

            // ---- QKV: 3 GEMVs x 4-way split-K across 384 threads, dual-element ----
            if (tid < 384) {
                int w = tid >> 7;           // 0=Q,1=K,2=V
                int sub = tid & 127;
                int cc = sub & 31, q4 = sub >> 5;
                float a0[4] = {}, a1[4] = {};
                gemv4_dual<32>(ht[0], ht[1], W + w * DIM * DIM, cc, q4 * 32, a0, a1);
                int base = (w * 4 + q4) * 256;
                *(float4*)&pb[base + cc * 4]       = make_float4(a0[0], a0[1], a0[2], a0[3]);
                *(float4*)&pb[base + 128 + cc * 4] = make_float4(a1[0], a1[1], a1[2], a1[3]);
            }
            __syncthreads();
            {
                // combine 768 outputs: (w, el, d)
                int p = tid;
                if (p < 768) {
                    int w = p >> 8;          // 0..2
                    int el = (p >> 7) & 1;
                    int d = p & 127;
                    float s = bb[w * DIM + d];
#pragma unroll
                    for (int qq = 0; qq < 4; qq++) s += pb[(w * 4 + qq) * 256 + el * 128 + d];
                    if (w == 0) {
                        sq[el][d] = s;
                    } else {
                        int cb = ((l * BB + b0 + el) * NH + (d >> 4)) * NNOD * DHE + t * DHE + (d & 15);
                        if (w == 1) Kc[cb] = s; else Vc[cb] = s;
                    }
                }
                // p in [512,768) handled by first 256 threads' second pass:
                if (tid < 256) {
                    int p2 = tid + 512;
                    int el = (p2 >> 7) & 1;
                    int d = p2 & 127;
                    float s = bb[2 * DIM + d];
#pragma unroll
                    for (int qq = 0; qq < 4; qq++) s += pb[(2 * 4 + qq) * 256 + el * 128 + d];
                    int cb = ((l * BB + b0 + el) * NH + (d >> 4)) * NNOD * DHE + t * DHE + (d & 15);
                    Vc[cb] = s;
                }
            }
            __syncthreads();

            // ---- self-attn scores ----
            int nt = t + 1;
            for (int p = tid; p < 2 * NH * nt; p += 512) {
                int el = p / (NH * nt);
                int r = p % (NH * nt);
                int ph = r / nt, ps = r % nt;
                const float* kp = &Kc[((l * BB + b0 + el) * NH + ph) * NNOD * DHE + ps * DHE];
                const float* qp = &sq[el][ph * DHE];
                float s = 0.f;
#pragma unroll
                for (int j = 0; j < DHE; j++) s += qp[j] * kp[j];
                sc[el][ph][ps] = s * 0.25f;
            }
            __syncthreads();
            if (tid < 16) {
                int el = tid >> 3, h = tid & 7;
                float mx = -1e30f;
                for (int s = 0; s < nt; s++) mx = fmaxf(mx, sc[el][h][s]);
                float sm = 0.f;
                for (int s = 0; s < nt; s++) { float e = expf(sc[el][h][s] - mx); sc[el][h][s] = e; sm += e; }
                float inv = 1.f / sm;
                for (int s = 0; s < nt; s++) sc[el][h][s] *= inv;
            }
            __syncthreads();
            // ---- V-weighted sum: (el, d, half) ----
            {
                int el = tid >> 8;
                int half = (tid >> 7) & 1;
                int d = tid & 127;
                int hh = d >> 4, dh = d & 15;
                int s0 = (nt * half) >> 1, s1 = (nt * (half + 1)) >> 1;
                const float* vp = &Vc[((l * BB + b0 + el) * NH + hh) * NNOD * DHE + dh];
                float oo = 0.f;
#pragma unroll 4
                for (int s = s0; s < s1; s++) oo += sc[el][hh][s] * vp[s * DHE];
                pb[el * 256 + half * 128 + d] = oo;
            }
            __syncthreads();
            if (tid < 256) {
                int el = tid >> 7, d = tid & 127;
                so[el][d] = pb[el * 256 + d] + pb[el * 256 + 128 + d];
            }
            __syncthreads();
            // ---- Wo + residual ----
            {
                float a0[4] = {}, a1[4] = {};
                gemv4_dual<8>(so[0], so[1], W + 3 * DIM * DIM, c, q16 * 8, a0, a1);
                *(float4*)&pb[q16 * 256 + c * 4]       = make_float4(a0[0], a0[1], a0[2], a0[3]);
                *(float4*)&pb[q16 * 256 + 128 + c * 4] = make_float4(a1[0], a1[1], a1[2], a1[3]);
            }
            __syncthreads();
            if (tid < 256) {
                int el = tid >> 7, d = tid & 127;
                float s = ht[el][d] + bb[3 * DIM + d];
#pragma unroll
                for (int qq = 0; qq < 16; qq++) s += pb[qq * 256 + el * 128 + d];
                su[el][d] = s;
            }
            __syncthreads();
            {
                // per-element layernorm: el = tid>>8, 256 threads each, d appears twice
                const float* gb = dln + ((l * 3 + 0) * 2) * DIM;
                int el = tid >> 8, d = tid & 127;
                float v = su[el][d];
#pragma unroll
                for (int o = 16; o; o >>= 1) v += __shfl_down_sync(0xffffffffu, v, o);
                if ((tid & 31) == 0) red[tid >> 5] = v;
                __syncthreads();
                float r = 0.f;
#pragma unroll
                for (int i = 0; i < 8; i++) r += red[el * 8 + i];
                float mean = r * (1.f / 256.f);
                float diff = su[el][d] - mean;
                float vv = diff * diff;
#pragma unroll
                for (int o = 16; o; o >>= 1) vv += __shfl_down_sync(0xffffffffu, vv, o);
                __syncthreads();
                if ((tid & 31) == 0) red[tid >> 5] = vv;
                __syncthreads();
                float r2 = 0.f;
#pragma unroll
                for (int i = 0; i < 8; i++) r2 += red[el * 8 + i];
                float rstd = rsqrtf(r2 * (1.f / 256.f) + 1e-5f);
                if (tid < 256) ht[el][d] = gb[d] * diff * rstd + gb[DIM + d];
                else { int el1 = 1; ht[el1][d] = gb[d] * diff * rstd + gb[DIM + d]; }
                __syncthreads();
            }

            // ---- cross attention ----
            const float* Wc = dcw + l * 2 * DIM * DIM;
            const float* bc = dcb + l * 2 * DIM;
            {
                float a0[4] = {}, a1[4] = {};
                gemv4_dual<8>(ht[0], ht[1], Wc, c, q16 * 8, a0, a1);
                *(float4*)&pb[q16 * 256 + c * 4]       = make_float4(a0[0], a0[1], a0[2], a0[3]);
                *(float4*)&pb[q16 * 256 + 128 + c * 4] = make_float4(a1[0], a1[1], a1[2], a1[3]);
            }
            __syncthreads();
            if (tid < 256) {
                int el = tid >> 7, d = tid & 127;
                float s = bc[d];
#pragma unroll
                for (int qq = 0; qq < 16; qq++) s += pb[qq * 256 + el * 128 + d];
                sq[el][d] = s;
            }
            __syncthreads();
            for (int p = tid; p < 2 * NH * SEQ; p += 512) {
                int el = p / (NH * SEQ);
                int r = p % (NH * SEQ);
                int ph = r / SEQ, pn = r % SEQ;
                const float* kp = &Katt[((b0 + el) * SEQ + pn) * (NLD * DIM) + l * DIM + ph * DHE];
                const float* qp = &sq[el][ph * DHE];
                float s = 0.f;
#pragma unroll
                for (int j = 0; j < DHE; j++) s += qp[j] * kp[j];
                sc[el][ph][pn] = s * 0.25f;
            }
            __syncthreads();
            if (tid < 16) {
                int el = tid >> 3, h = tid & 7;
                float mx = -1e30f;
                for (int n = 0; n < SEQ; n++) mx = fmaxf(mx, sc[el][h][n]);
                float sm = 0.f;
                for (int n = 0; n < SEQ; n++) { float e = expf(sc[el][h][n] - mx); sc[el][h][n] = e; sm += e; }
                float inv = 1.f / sm;
                for (int n = 0; n < SEQ; n++) sc[el][h][n] *= inv;
            }
            __syncthreads();
            {
                int el = tid >> 8;
                int half = (tid >> 7) & 1;
                int d = tid & 127;
                int hh = d >> 4;
                int s0 = (SEQ * half) >> 1, s1 = (SEQ * (half + 1)) >> 1;
                const float* vp = &Vatt[(b0 + el) * SEQ * (NLD * DIM) + l * DIM + d];
                float oo = 0.f;
#pragma unroll 4
                for (int n = s0; n < s1; n++) oo += sc[el][hh][n] * vp[n * NLD * DIM];
                pb[el * 256 + half * 128 + d] = oo;
            }
            __syncthreads();
            if (tid < 256) {
                int el = tid >> 7, d = tid & 127;
                so[el][d] = pb[el * 256 + d] + pb[el * 256 + 128 + d];
            }
            __syncthreads();
            {
                float a0[4] = {}, a1[4] = {};
                gemv4_dual<8>(so[0], so[1], Wc + DIM * DIM, c, q16 * 8, a0, a1);
                *(float4*)&pb[q16 * 256 + c * 4]       = make_float4(a0[0], a0[1], a0[2], a0[3]);
                *(float4*)&pb[q16 * 256 + 128 + c * 4] = make_float4(a1[0], a1[1], a1[2], a1[3]);
            }
            __syncthreads();
            if (tid < 256) {
                int el = tid >> 7, d = tid & 127;
                float s = ht[el][d] + bc[DIM + d];
#pragma unroll
                for (int qq = 0; qq < 16; qq++) s += pb[qq * 256 + el * 128 + d];
                su[el][d] = s;
            }
            __syncthreads();
            {
                const float* gb = dln + ((l * 3 + 1) * 2) * DIM;
                int el = tid >> 8, d = tid & 127;
                float v = su[el][d];
#pragma unroll
                for (int o = 16; o; o >>= 1) v += __shfl_down_sync(0xffffffffu, v, o);
                if ((tid & 31) == 0) red[tid >> 5] = v;
                __syncthreads();
                float r = 0.f;
#pragma unroll
                for (int i = 0; i < 8; i++) r += red[el * 8 + i];
                float mean = r * (1.f / 256.f);
                float diff = su[el][d] - mean;
                float vv = diff * diff;
#pragma unroll
                for (int o = 16; o; o >>= 1) vv += __shfl_down_sync(0xffffffffu, vv, o);
                __syncthreads();
                if ((tid & 31) == 0) red[tid >> 5] = vv;
                __syncthreads();
                float r2 = 0.f;
#pragma unroll
                for (int i = 0; i < 8; i++) r2 += red[el * 8 + i];
                float rstd = rsqrtf(r2 * (1.f / 256.f) + 1e-5f);
                ht[el][d] = gb[d] * diff * rstd + gb[DIM + d];
                __syncthreads();
            }

            // ---- FFN1: [128 -> 512], (cc 0..127, q4) dual-element ----
            {
                int cc = tid & 127, q4 = tid >> 7;
                const float* W1 = dw1 + l * DIM * FFD;
                const float4* Wp = (const float4*)(W1 + (q4 * 32) * FFD) + cc;
                const float* xp0 = ht[0] + q4 * 32;
                const float* xp1 = ht[1] + q4 * 32;
                float a0[4] = {}, a1[4] = {};
#pragma unroll
                for (int k = 0; k < 32; k++) {
                    float4 w = Wp[k * 128];
                    float v0 = xp0[k], v1 = xp1[k];
                    a0[0] += v0 * w.x; a0[1] += v0 * w.y; a0[2] += v0 * w.z; a0[3] += v0 * w.w;
                    a1[0] += v1 * w.x; a1[1] += v1 * w.y; a1[2] += v1 * w.z; a1[3] += v1 * w.w;
                }
                *(float4*)&pb[q4 * 1024 + cc * 4]       = make_float4(a0[0], a0[1], a0[2], a0[3]);
                *(float4*)&pb[q4 * 1024 + 512 + cc * 4] = make_float4(a1[0], a1[1], a1[2], a1[3]);
            }
            __syncthreads();
            for (int p = tid; p < 2 * FFD; p += 512) {
                int el = p >> 9, o = p & 511;
                float s = db1[l * FFD + o];
#pragma unroll
                for (int qq = 0; qq < 4; qq++) s += pb[qq * 1024 + el * 512 + o];
                sf[el][o] = fmaxf(s, 0.f);
            }
            __syncthreads();
            // ---- FFN2: [512 -> 128], (c, q16) dual-element, 32 k each ----
            {
                const float* W2 = dw2 + l * FFD * DIM;
                const float4* Wp = (const float4*)(W2 + (q16 * 32) * DIM) + c;
                const float* xp0 = sf[0] + q16 * 32;
                const float* xp1 = sf[1] + q16 * 32;
                float a0[4] = {}, a1[4] = {};
#pragma unroll
                for (int k = 0; k < 32; k++) {
                    float4 w = Wp[k * 32];
                    float v0 = xp0[k], v1 = xp1[k];
                    a0[0] += v0 * w.x; a0[1] += v0 * w.y; a0[2] += v0 * w.z; a0[3] += v0 * w.w;
                    a1[0] += v1 * w.x; a1[1] += v1 * w.y; a1[2] += v1 * w.z; a1[3] += v1 * w.w;
                }
                *(float4*)&pb[q16 * 256 + c * 4]       = make_float4(a0[0], a0[1], a0[2], a0[3]);
                *(float4*)&pb[q16 * 256 + 128 + c * 4] = make_float4(a1[0], a1[1], a1[2], a1[3]);
            }
            __syncthreads();
            if (tid < 256) {
                int el = tid >> 7, d = tid & 127;
                float s = ht[el][d] + db2[l * DIM + d];
#pragma unroll
                for (int qq = 0; qq < 16; qq++) s += pb[qq * 256 + el * 128 + d];
                su[el][d] = s;
            }
            __syncthreads();
            {
                const float* gb = dln + ((l * 3 + 2) * 2) * DIM;
                int el = tid >> 8, d = tid & 127;
                float v = su[el][d];
#pragma unroll
                for (int o = 16; o; o >>= 1) v += __shfl_down_sync(0xffffffffu, v, o);
                if ((tid & 31) == 0) red[tid >> 5] = v;
                __syncthreads();
                float r = 0.f;
#pragma unroll
                for (int i = 0; i < 8; i++) r += red[el * 8 + i];
                float mean = r * (1.f / 256.f);
                float diff = su[el][d] - mean;
                float vv = diff * diff;
#pragma unroll
                for (int o = 16; o; o >>= 1) vv += __shfl_down_sync(0xffffffffu, vv, o);
                __syncthreads();
                if ((tid & 31) == 0) red[tid >> 5] = vv;
                __syncthreads();
                float r2 = 0.f;
#pragma unroll
                for (int i = 0; i < 8; i++) r2 += red[el * 8 + i];
                float rstd = rsqrtf(r2 * (1.f / 256.f) + 1e-5f);
                ht[el][d] = gb[d] * diff * rstd + gb[DIM + d];
                __syncthreads();
            }
        }

        // ---- final pointer logits ----
        {
            float a0[4] = {}, a1[4] = {};
            gemv4_dual<8>(ht[0], ht[1], wqf, c, q16 * 8, a0, a1);
            *(float4*)&pb[q16 * 256 + c * 4]       = make_float4(a0[0], a0[1], a0[2], a0[3]);
            *(float4*)&pb[q16 * 256 + 128 + c * 4] = make_float4(a1[0], a1[1], a1[2], a1[3]);
        }
        __syncthreads();
        if (tid < 256) {
            int el = tid >> 7, d = tid & 127;
            float s = 0.f;
#pragma unroll
            for (int qq = 0; qq < 16; qq++) s += pb[qq * 256 + el * 128 + d];
            sq[el][d] = s;
        }
        __syncthreads();
        for (int p = tid; p < 2 * SEQ; p += 512) {
            int el = p / SEQ, n = p % SEQ;
            const float4* kp = (const float4*)&Kfin[((b0 + el) * SEQ + n) * DIM];
            const float* sqe = sq[el];
            float s = 0.f;
#pragma unroll
            for (int k = 0; k < 32; k++) {
                float4 kv = kp[k];
                s += sqe[4 * k] * kv.x + sqe[4 * k + 1] * kv.y
                   + sqe[4 * k + 2] * kv.z + sqe[4 * k + 3] * kv.w;
            }
            float lg = 10.f * tanhf(s * 0.08838834764831845f);   // 1/sqrt(128)
            slg[el][n] = smask[el][n] ? -1e9f : lg;
        }
        __syncthreads();
        if (tid < 2) {
            int el = tid;
            float mx = -1e30f;
            int am = 0;
            for (int n = 0; n < SEQ; n++) if (slg[el][n] > mx) { mx = slg[el][n]; am = n; }
            float sm = 0.f;
            for (int n = 0; n < SEQ; n++) sm += expf(slg[el][n] - mx);
            sslp[el] += -logf(sm);
            smask[el][am] = 1;
            scur[el] = am;
            out[(b0 + el) * NNOD + t] = (float)am;
        }
        __syncthreads();
    }
    if (tid < 2) out[BB * NNOD + b0 + tid] = sslp[tid];
}

// ---------------- host launcher ----------------
extern "C" void kernel_launch(void* const* d_in, const int* in_sizes, int n_in,
                              void* d_out, int out_size)
{
    const float* x          = (const float*)d_in[0];
    const float* w_input    = (const float*)d_in[1];
    const float* b_input    = (const float*)d_in[2];
    const float* start_ph   = (const float*)d_in[3];
    const float* enc_attn_w = (const float*)d_in[4];
    const float* enc_attn_b = (const float*)d_in[5];
    const float* enc_ffn_w1 = (const float*)d_in[6];
    const float* enc_ffn_b1 = (const float*)d_in[7];
    const float* enc_ffn_w2 = (const float*)d_in[8];
    const float* enc_ffn_b2 = (const float*)d_in[9];
    const float* enc_bn     = (const float*)d_in[10];
    const float* dec_self_w = (const float*)d_in[11];
    const float* dec_self_b = (const float*)d_in[12];
    const float* dec_cross_w= (const float*)d_in[13];
    const float* dec_cross_b= (const float*)d_in[14];
    const float* dec_ffn_w1 = (const float*)d_in[15];
    const float* dec_ffn_b1 = (const float*)d_in[16];
    const float* dec_ffn_w2 = (const float*)d_in[17];
    const float* dec_ffn_b2 = (const float*)d_in[18];
    const float* dec_ln     = (const float*)d_in[19];
    const float* wk_dec     = (const float*)d_in[20];
    const float* bk_dec     = (const float*)d_in[21];
    const float* wv_dec     = (const float*)d_in[22];
    const float* bv_dec     = (const float*)d_in[23];
    const float* wq_final   = (const float*)d_in[24];
    const float* wk_final   = (const float*)d_in[25];
    float* out = (float*)d_out;

    float* base = nullptr;
    cudaGetSymbolAddress((void**)&base, g_scratch);
    float* ph    = base;
    float* pt    = base + OFF_T;
    float* pQ    = base + OFF_Q;
    float* pf    = base + OFF_F;
    float* pKatt = base + OFF_KATT;
    float* pVatt = base + OFF_VATT;
    float* pKfin = base + OFF_KFIN;
    float* ppart = base + OFF_PART;
    float* pmean = base + OFF_MEAN;
    float* prstd = base + OFF_RSTD;
    float* ppe   = base + OFF_PE;
    float* pKc   = base + OFF_KC;
    float* pVc   = base + OFF_VC;

    embed_kernel<<<(MTOT * DIM + 255) / 256, 256>>>(x, w_input, b_input, start_ph, ph);
    pe_kernel<<<(NNOD * DIM + 255) / 256, 256>>>(ppe);

    dim3 gDD(DIM / 64, MTOT / 64);            // N=128
    dim3 gQKV(DIM / 64, MTOT / 64, 3);        // fused Q,K,V
    dim3 gDF(FFD / 64, MTOT / 64);            // N=512
    dim3 gD2(256 / 64, MTOT / 64);            // N=256

    for (int l = 0; l < NLE; l++) {
        const float* aw = enc_attn_w + (size_t)l * 4 * DIM * DIM;
        const float* ab = enc_attn_b + (size_t)l * 4 * DIM;
        sgemm<true, false, false, true><<<gQKV, 256>>>(ph, aw, ab, nullptr, pQ, MTOT, DIM, DIM);
        enc_attn<<<BB * NH, 128>>>(pQ, pQ + SZ_MD, pQ + 2 * SZ_MD, base + OFF_O);
        sgemm<true, false, true, false><<<gDD, 256>>>(base + OFF_O, aw + 3 * DIM * DIM,
                 ab + 3 * DIM, ph, pt, MTOT, DIM, DIM);
        bn_partial<<<64, 256>>>(pt, ppart);
        bn_reduce<<<1, 128>>>(ppart, pmean, prstd);
        bn_apply<<<(MTOT * DIM + 255) / 256, 256>>>(pt, pmean, prstd,
                 enc_bn + ((l * 2 + 0) * 2 + 0) * DIM, enc_bn + ((l * 2 + 0) * 2 + 1) * DIM, ph);
        sgemm<true, true, false, false><<<gDF, 256>>>(ph, enc_ffn_w1 + (size_t)l * DIM * FFD,
                 enc_ffn_b1 + (size_t)l * FFD, nullptr, pf, MTOT, FFD, DIM);
        sgemm<true, false, true, false><<<gDD, 256>>>(pf, enc_ffn_w2 + (size_t)l * FFD * DIM,
                 enc_ffn_b2 + (size_t)l * DIM, ph, pt, MTOT, DIM, FFD);
        bn_partial<<<64, 256>>>(pt, ppart);
        bn_reduce<<<1, 128>>>(ppart, pmean, prstd);
        bn_apply<<<(MTOT * DIM + 255) / 256, 256>>>(pt, pmean, prstd,
                 enc_bn + ((l * 2 + 1) * 2 + 0) * DIM, enc_bn + ((l * 2 + 1) * 2 + 1) * DIM, ph);
    }

    sgemm<true,  false, false, false><<<gD2, 256>>>(ph, wk_dec,   bk_dec,  nullptr, pKatt, MTOT, NLD * DIM, DIM);
    sgemm<true,  false, false, false><<<gD2, 256>>>(ph, wv_dec,   bv_dec,  nullptr, pVatt, MTOT, NLD * DIM, DIM);
    sgemm<false, false, false, false><<<gDD, 256>>>(ph, wk_final, nullptr, nullptr, pKfin, MTOT, DIM, DIM);

    decoder_kernel<<<BB / 2, 512>>>(ph, ppe, pKatt, pVatt, pKfin, pKc, pVc,
                                dec_self_w, dec_self_b, dec_cross_w, dec_cross_b,
                                dec_ffn_w1, dec_ffn_b1, dec_ffn_w2, dec_ffn_b2,
                                dec_ln, wq_final, out);
}

// round 8
// speedup vs baseline: 1.0451x; 1.0451x over previous
#include <cuda_runtime.h>
#include <math.h>

#define BB   128
#define NNOD 50
#define SEQ  51
#define DIM  128
#define NH   8
#define DHE  16
#define FFD  512
#define NLE  6
#define NLD  2
#define MTOT (BB*SEQ)            // 6528
#define SZ_MD (MTOT*DIM)         // 835584

// ---------------- scratch ----------------
#define OFF_T    (SZ_MD)
#define OFF_Q    (2*SZ_MD)
#define OFF_O    (5*SZ_MD)
#define OFF_F    (6*SZ_MD)
#define OFF_KATT (10*SZ_MD)
#define OFF_VATT (12*SZ_MD)
#define OFF_KFIN (14*SZ_MD)
#define OFF_PART (15*SZ_MD)
#define OFF_MEAN (OFF_PART + 16384)
#define OFF_RSTD (OFF_MEAN + 128)
#define OFF_PE   (OFF_RSTD + 128)
#define OFF_KC   (OFF_PE + NNOD*DIM)
#define SZ_KC    (NLD*BB*NH*NNOD*DHE)
#define OFF_VC   (OFF_KC + SZ_KC)
#define SCRATCH_TOTAL (OFF_VC + SZ_KC)

__device__ float g_scratch[SCRATCH_TOTAL];

// ---------------- embedding ----------------
__global__ void embed_kernel(const float* __restrict__ x,
                             const float* __restrict__ w_in,
                             const float* __restrict__ b_in,
                             const float* __restrict__ start_ph,
                             float* __restrict__ h)
{
    int i = blockIdx.x * blockDim.x + threadIdx.x;
    if (i >= MTOT * DIM) return;
    int d = i & 127;
    int row = i >> 7;
    int s = row % SEQ;
    int b = row / SEQ;
    float v;
    if (s < NNOD) {
        const float* xp = x + (b * NNOD + s) * 2;
        v = xp[0] * w_in[d] + xp[1] * w_in[DIM + d] + b_in[d];
    } else {
        v = start_ph[d];
    }
    h[i] = v;
}

// ---------------- positional encoding ----------------
__global__ void pe_kernel(float* __restrict__ pe)
{
    int i = blockIdx.x * blockDim.x + threadIdx.x;
    if (i >= NNOD * DIM) return;
    int t = i >> 7, d = i & 127;
    double e = (double)(2 * (d / 2)) / 128.0;
    double ang = (double)t * pow(10000.0, -e);
    pe[i] = (float)(((d & 1) == 0) ? sin(ang) : cos(ang));
}

// ---------------- SGEMM (double-buffered): C = A[M,K] @ W[K,N] ----------------
template<bool BIAS, bool RELU, bool RES, bool ZSTRIDE>
__global__ void __launch_bounds__(256) sgemm(const float* __restrict__ A,
                                             const float* __restrict__ W,
                                             const float* __restrict__ bias,
                                             const float* __restrict__ R,
                                             float* __restrict__ C,
                                             int M, int N, int K)
{
    if (ZSTRIDE) {
        int z = blockIdx.z;
        W += (size_t)z * K * N;
        if (BIAS) bias += (size_t)z * N;
        C += (size_t)z * M * N;
    }
    __shared__ float As[2][16][68];
    __shared__ float Bs[2][16][68];
    int bm = blockIdx.y * 64, bn = blockIdx.x * 64;
    int tid = threadIdx.x;
    int tr = tid >> 4, tc = tid & 15;
    int mA = tid >> 2, kkA = (tid & 3) * 4;     // A tile load coords
    int krB = tid >> 4, ccB = (tid & 15) * 4;   // B tile load coords
    float acc[4][4] = {};

    // prologue: load k-panel 0 into buffer 0
    {
        float4 av = *(const float4*)&A[(bm + mA) * K + kkA];
        float4 bv = *(const float4*)&W[krB * N + bn + ccB];
        As[0][kkA + 0][mA] = av.x; As[0][kkA + 1][mA] = av.y;
        As[0][kkA + 2][mA] = av.z; As[0][kkA + 3][mA] = av.w;
        Bs[0][krB][ccB + 0] = bv.x; Bs[0][krB][ccB + 1] = bv.y;
        Bs[0][krB][ccB + 2] = bv.z; Bs[0][krB][ccB + 3] = bv.w;
    }
    __syncthreads();

    int buf = 0;
    for (int k0 = 0; k0 < K; k0 += 16) {
        bool more = (k0 + 16) < K;
        float4 av2, bv2;
        if (more) {
            av2 = *(const float4*)&A[(bm + mA) * K + k0 + 16 + kkA];
            bv2 = *(const float4*)&W[(k0 + 16 + krB) * N + bn + ccB];
        }
#pragma unroll
        for (int k2 = 0; k2 < 16; k2++) {
            float ra[4], rb[4];
#pragma unroll
            for (int i = 0; i < 4; i++) { ra[i] = As[buf][k2][tr * 4 + i]; rb[i] = Bs[buf][k2][tc * 4 + i]; }
#pragma unroll
            for (int i = 0; i < 4; i++)
#pragma unroll
                for (int j = 0; j < 4; j++) acc[i][j] += ra[i] * rb[j];
        }
        if (more) {
            As[buf ^ 1][kkA + 0][mA] = av2.x; As[buf ^ 1][kkA + 1][mA] = av2.y;
            As[buf ^ 1][kkA + 2][mA] = av2.z; As[buf ^ 1][kkA + 3][mA] = av2.w;
            Bs[buf ^ 1][krB][ccB + 0] = bv2.x; Bs[buf ^ 1][krB][ccB + 1] = bv2.y;
            Bs[buf ^ 1][krB][ccB + 2] = bv2.z; Bs[buf ^ 1][krB][ccB + 3] = bv2.w;
        }
        __syncthreads();
        buf ^= 1;
    }
#pragma unroll
    for (int i = 0; i < 4; i++) {
        int m = bm + tr * 4 + i;
#pragma unroll
        for (int j = 0; j < 4; j++) {
            int n = bn + tc * 4 + j;
            float v = acc[i][j];
            if (BIAS) v += bias[n];
            if (RELU) v = fmaxf(v, 0.f);
            if (RES)  v += R[m * N + n];
            C[m * N + n] = v;
        }
    }
}

// ---------------- encoder attention v2: 256 threads, warp-parallel softmax ----------------
__global__ void __launch_bounds__(256) enc_attn(const float* __restrict__ Q,
                                                const float* __restrict__ K,
                                                const float* __restrict__ V,
                                                float* __restrict__ O)
{
    __shared__ float Qs[SEQ][DHE], Ks[SEQ][DHE], Vs[SEQ][DHE];
    __shared__ float P[SEQ][SEQ + 1];
    int bh = blockIdx.x;
    int b = bh / NH, hh = bh % NH;
    int tid = threadIdx.x;
    // float4 tile loads: 51 rows x 4 float4 per matrix
    for (int i = tid; i < SEQ * 4; i += 256) {
        int s = i >> 2, j4 = (i & 3) * 4;
        int g = (b * SEQ + s) * DIM + hh * DHE + j4;
        *(float4*)&Qs[s][j4] = *(const float4*)&Q[g];
        *(float4*)&Ks[s][j4] = *(const float4*)&K[g];
        *(float4*)&Vs[s][j4] = *(const float4*)&V[g];
    }
    __syncthreads();
    for (int p = tid; p < SEQ * SEQ; p += 256) {
        int q = p / SEQ, k = p % SEQ;
        float s = 0.f;
#pragma unroll
        for (int j = 0; j < DHE; j++) s += Qs[q][j] * Ks[k][j];
        P[q][k] = s * 0.25f;
    }
    __syncthreads();
    // warp-per-row softmax: warp w handles rows w, w+8, ...
    {
        int w = tid >> 5, lane = tid & 31;
        for (int q = w; q < SEQ; q += 8) {
            float v0 = (lane < SEQ) ? P[q][lane] : -1e30f;
            float v1 = (lane + 32 < SEQ) ? P[q][lane + 32] : -1e30f;
            float mx = fmaxf(v0, v1);
#pragma unroll
            for (int o = 16; o; o >>= 1) mx = fmaxf(mx, __shfl_xor_sync(0xffffffffu, mx, o));
            float e0 = (lane < SEQ) ? expf(v0 - mx) : 0.f;
            float e1 = (lane + 32 < SEQ) ? expf(v1 - mx) : 0.f;
            float sm = e0 + e1;
#pragma unroll
            for (int o = 16; o; o >>= 1) sm += __shfl_xor_sync(0xffffffffu, sm, o);
            float inv = 1.f / sm;
            if (lane < SEQ) P[q][lane] = e0 * inv;
            if (lane + 32 < SEQ) P[q][lane + 32] = e1 * inv;
        }
    }
    __syncthreads();
    for (int p = tid; p < SEQ * DHE; p += 256) {
        int q = p >> 4, j = p & 15;
        float s = 0.f;
        for (int k = 0; k < SEQ; k++) s += P[q][k] * Vs[k][j];
        O[(b * SEQ + q) * DIM + hh * DHE + j] = s;
    }
}

// ---------------- BatchNorm (deterministic 3-stage) ----------------
__global__ void __launch_bounds__(256) bn_partial(const float* __restrict__ X,
                                                  float* __restrict__ part)
{
    int d = threadIdx.x & 127, half = threadIdx.x >> 7;
    int r0 = blockIdx.x * 102;
    float s = 0.f, ss = 0.f;
    for (int r = r0 + half; r < r0 + 102; r += 2) {
        float v = X[r * DIM + d];
        s += v; ss += v * v;
    }
    __shared__ float sh[2][2][128];
    sh[half][0][d] = s; sh[half][1][d] = ss;
    __syncthreads();
    if (!half) {
        part[blockIdx.x * 256 + d]       = s + sh[1][0][d];
        part[blockIdx.x * 256 + 128 + d] = ss + sh[1][1][d];
    }
}

__global__ void bn_reduce(const float* __restrict__ part,
                          float* __restrict__ mean, float* __restrict__ rstd)
{
    int d = threadIdx.x;
    float s = 0.f, ss = 0.f;
    for (int b = 0; b < 64; b++) { s += part[b * 256 + d]; ss += part[b * 256 + 128 + d]; }
    float m = s * (1.f / (float)MTOT);
    float v = ss * (1.f / (float)MTOT) - m * m;
    mean[d] = m;
    rstd[d] = rsqrtf(v + 1e-5f);
}

__global__ void __launch_bounds__(256) bn_apply(const float* __restrict__ X,
                                                const float* __restrict__ mean,
                                                const float* __restrict__ rstd,
                                                const float* __restrict__ gamma,
                                                const float* __restrict__ beta,
                                                float* __restrict__ Y)
{
    int i = blockIdx.x * blockDim.x + threadIdx.x;
    if (i >= MTOT * DIM) return;
    int d = i & 127;
    Y[i] = gamma[d] * (X[i] - mean[d]) * rstd[d] + beta[d];
}

// ---------------- decoder helpers ----------------
__device__ __forceinline__ float blksum512(float v, float* red)
{
#pragma unroll
    for (int o = 16; o; o >>= 1) v += __shfl_down_sync(0xffffffffu, v, o);
    int w = threadIdx.x >> 5;
    if ((threadIdx.x & 31) == 0) red[w] = v;
    __syncthreads();
    float r = 0.f;
#pragma unroll
    for (int i = 0; i < 16; i++) r += red[i];
    __syncthreads();
    return r;
}

// float4 partial of a [128 -> 128] GEMV: 32 col-groups (c) x 16 k-groups (q16), 8 k each.
__device__ __forceinline__ void gemv4_part(const float* __restrict__ x,
                                           const float* __restrict__ W,
                                           int c, int q16, float* acc)
{
    const float4* Wp = (const float4*)(W + (q16 * 8) * DIM) + c;
    const float* xp = x + q16 * 8;
#pragma unroll
    for (int k = 0; k < 8; k++) {
        float xk = xp[k];
        float4 w = Wp[k * 32];
        acc[0] += xk * w.x; acc[1] += xk * w.y;
        acc[2] += xk * w.z; acc[3] += xk * w.w;
    }
}

// ---------------- persistent decoder: 1 batch element per block, 512 threads ----------------
__global__ void __launch_bounds__(512) decoder_kernel(
    const float* __restrict__ h_enc, const float* __restrict__ pe,
    const float* __restrict__ Katt, const float* __restrict__ Vatt,
    const float* __restrict__ Kfin,
    float* __restrict__ Kc, float* __restrict__ Vc,
    const float* __restrict__ dsw, const float* __restrict__ dsb,
    const float* __restrict__ dcw, const float* __restrict__ dcb,
    const float* __restrict__ dw1, const float* __restrict__ db1,
    const float* __restrict__ dw2, const float* __restrict__ db2,
    const float* __restrict__ dln, const float* __restrict__ wqf,
    float* __restrict__ out)
{
    int tid = threadIdx.x;
    int b = blockIdx.x;
    int d = tid & 127;           // output column (combine phases)
    int q4 = tid >> 7;           // 4-way group (attention splits / FFN1 k-groups)
    int c = tid & 31;            // col-group: columns 4c..4c+3
    int q16 = tid >> 5;          // 16-way k-group
    int hh = d >> 4, dh = d & 15;

    __shared__ float ht[DIM], sq[DIM], so[DIM], su[DIM];
    __shared__ float sf[FFD];
    __shared__ float pb0[2048], pb1[2048], pb2[2048];   // partial buffers
    __shared__ float sc[NH][SEQ + 1];
    __shared__ float red[16];
    __shared__ float slg[SEQ];
    __shared__ int   smask[SEQ];
    __shared__ int   scur;
    __shared__ float sslp;

    if (tid < SEQ) smask[tid] = (tid == NNOD) ? 1 : 0;
    if (tid == 0) { scur = NNOD; sslp = 0.f; }
    __syncthreads();

    for (int t = 0; t < NNOD; t++) {
        if (q4 == 0) ht[d] = h_enc[(b * SEQ + scur) * DIM + d] + pe[t * DIM + d];
        __syncthreads();

        for (int l = 0; l < NLD; l++) {
            const float* W  = dsw + l * 4 * DIM * DIM;
            const float* bb = dsb + l * 4 * DIM;

            // ---- QKV: three simultaneous float4 split-K partials ----
            {
                float aq[4] = {}, ak[4] = {}, av[4] = {};
                gemv4_part(ht, W,                 c, q16, aq);
                gemv4_part(ht, W + DIM * DIM,     c, q16, ak);
                gemv4_part(ht, W + 2 * DIM * DIM, c, q16, av);
                *(float4*)&pb0[q16 * 128 + c * 4] = make_float4(aq[0], aq[1], aq[2], aq[3]);
                *(float4*)&pb1[q16 * 128 + c * 4] = make_float4(ak[0], ak[1], ak[2], ak[3]);
                *(float4*)&pb2[q16 * 128 + c * 4] = make_float4(av[0], av[1], av[2], av[3]);
            }
            __syncthreads();
            {
                int cb = ((l * BB + b) * NH) * NNOD * DHE;
                if (tid < 128) {
                    float s = bb[tid];
#pragma unroll
                    for (int qq = 0; qq < 16; qq++) s += pb0[qq * 128 + tid];
                    sq[tid] = s;
                } else if (tid < 256) {
                    int dd = tid - 128;
                    float s = bb[DIM + dd];
#pragma unroll
                    for (int qq = 0; qq < 16; qq++) s += pb1[qq * 128 + dd];
                    Kc[cb + (dd >> 4) * NNOD * DHE + t * DHE + (dd & 15)] = s;
                } else if (tid < 384) {
                    int dd = tid - 256;
                    float s = bb[2 * DIM + dd];
#pragma unroll
                    for (int qq = 0; qq < 16; qq++) s += pb2[qq * 128 + dd];
                    Vc[cb + (dd >> 4) * NNOD * DHE + t * DHE + (dd & 15)] = s;
                }
            }
            __syncthreads();

            // ---- self-attn scores ----
            int nt = t + 1;
            if (tid < NH * nt) {
                int ph = tid / nt, ps = tid % nt;
                const float* kp = &Kc[((l * BB + b) * NH + ph) * NNOD * DHE + ps * DHE];
                const float* qp = &sq[ph * DHE];
                float s = 0.f;
#pragma unroll
                for (int j = 0; j < DHE; j++) s += qp[j] * kp[j];
                sc[ph][ps] = s * 0.25f;
            }
            __syncthreads();
            if (tid < NH) {
                float mx = -1e30f;
                for (int s = 0; s < nt; s++) mx = fmaxf(mx, sc[tid][s]);
                float sm = 0.f;
                for (int s = 0; s < nt; s++) { float e = expf(sc[tid][s] - mx); sc[tid][s] = e; sm += e; }
                float inv = 1.f / sm;
                for (int s = 0; s < nt; s++) sc[tid][s] *= inv;
            }
            __syncthreads();
            // ---- V-weighted sum, s-range split across q4 groups ----
            {
                int s0 = (nt * q4) >> 2, s1 = (nt * (q4 + 1)) >> 2;
                const float* vp = &Vc[((l * BB + b) * NH + hh) * NNOD * DHE + dh];
                float oo = 0.f;
#pragma unroll 4
                for (int s = s0; s < s1; s++) oo += sc[hh][s] * vp[s * DHE];
                pb0[q4 * 128 + d] = oo;
            }
            __syncthreads();
            if (tid < 128) so[tid] = pb0[tid] + pb0[128 + tid] + pb0[256 + tid] + pb0[384 + tid];
            __syncthreads();
            // ---- Wo + residual ----
            {
                float a[4] = {};
                gemv4_part(so, W + 3 * DIM * DIM, c, q16, a);
                *(float4*)&pb0[q16 * 128 + c * 4] = make_float4(a[0], a[1], a[2], a[3]);
            }
            __syncthreads();
            if (tid < 128) {
                float s = ht[tid] + bb[3 * DIM + tid];
#pragma unroll
                for (int qq = 0; qq < 16; qq++) s += pb0[qq * 128 + tid];
                su[tid] = s;
            }
            __syncthreads();
            {
                const float* gb = dln + ((l * 3 + 0) * 2) * DIM;
                float mean = blksum512(su[d], red) * (1.f / 512.f);
                float diff = su[d] - mean;
                float var = blksum512(diff * diff, red) * (1.f / 512.f);
                float rstd = rsqrtf(var + 1e-5f);
                if (q4 == 0) ht[d] = gb[d] * diff * rstd + gb[DIM + d];
                __syncthreads();
            }

            // ---- cross attention ----
            const float* Wc = dcw + l * 2 * DIM * DIM;
            const float* bc = dcb + l * 2 * DIM;
            {
                float a[4] = {};
                gemv4_part(ht, Wc, c, q16, a);
                *(float4*)&pb0[q16 * 128 + c * 4] = make_float4(a[0], a[1], a[2], a[3]);
            }
            __syncthreads();
            if (tid < 128) {
                float s = bc[tid];
#pragma unroll
                for (int qq = 0; qq < 16; qq++) s += pb0[qq * 128 + tid];
                sq[tid] = s;
            }
            __syncthreads();
            if (tid < NH * SEQ) {
                int ph = tid / SEQ, pn = tid % SEQ;
                const float* kp = &Katt[(b * SEQ + pn) * (NLD * DIM) + l * DIM + ph * DHE];
                const float* qp = &sq[ph * DHE];
                float s = 0.f;
#pragma unroll
                for (int j = 0; j < DHE; j++) s += qp[j] * kp[j];
                sc[ph][pn] = s * 0.25f;
            }
            __syncthreads();
            if (tid < NH) {
                float mx = -1e30f;
                for (int n = 0; n < SEQ; n++) mx = fmaxf(mx, sc[tid][n]);
                float sm = 0.f;
                for (int n = 0; n < SEQ; n++) { float e = expf(sc[tid][n] - mx); sc[tid][n] = e; sm += e; }
                float inv = 1.f / sm;
                for (int n = 0; n < SEQ; n++) sc[tid][n] *= inv;
            }
            __syncthreads();
            {
                int s0 = (SEQ * q4) >> 2, s1 = (SEQ * (q4 + 1)) >> 2;
                const float* vp = &Vatt[b * SEQ * (NLD * DIM) + l * DIM + d];
                float oo = 0.f;
#pragma unroll 4
                for (int n = s0; n < s1; n++) oo += sc[hh][n] * vp[n * NLD * DIM];
                pb0[q4 * 128 + d] = oo;
            }
            __syncthreads();
            if (tid < 128) so[tid] = pb0[tid] + pb0[128 + tid] + pb0[256 + tid] + pb0[384 + tid];
            __syncthreads();
            {
                float a[4] = {};
                gemv4_part(so, Wc + DIM * DIM, c, q16, a);
                *(float4*)&pb0[q16 * 128 + c * 4] = make_float4(a[0], a[1], a[2], a[3]);
            }
            __syncthreads();
            if (tid < 128) {
                float s = ht[tid] + bc[DIM + tid];
#pragma unroll
                for (int qq = 0; qq < 16; qq++) s += pb0[qq * 128 + tid];
                su[tid] = s;
            }
            __syncthreads();
            {
                const float* gb = dln + ((l * 3 + 1) * 2) * DIM;
                float mean = blksum512(su[d], red) * (1.f / 512.f);
                float diff = su[d] - mean;
                float var = blksum512(diff * diff, red) * (1.f / 512.f);
                float rstd = rsqrtf(var + 1e-5f);
                if (q4 == 0) ht[d] = gb[d] * diff * rstd + gb[DIM + d];
                __syncthreads();
            }

            // ---- FFN1: [128 -> 512], 128 col-groups (cc) x 4 k-groups (q4), 32 k each ----
            {
                int cc = tid & 127;
                const float* W1 = dw1 + l * DIM * FFD;
                const float4* Wp = (const float4*)(W1 + (q4 * 32) * FFD) + cc;
                const float* xp = ht + q4 * 32;
                float a[4] = {};
#pragma unroll
                for (int k = 0; k < 32; k++) {
                    float xk = xp[k];
                    float4 w = Wp[k * 128];
                    a[0] += xk * w.x; a[1] += xk * w.y;
                    a[2] += xk * w.z; a[3] += xk * w.w;
                }
                *(float4*)&pb0[q4 * 512 + cc * 4] = make_float4(a[0], a[1], a[2], a[3]);
            }
            __syncthreads();
            sf[tid] = fmaxf(db1[l * FFD + tid] + pb0[tid] + pb0[512 + tid]
                            + pb0[1024 + tid] + pb0[1536 + tid], 0.f);
            __syncthreads();
            // ---- FFN2: [512 -> 128], 32 col-groups (c) x 16 k-groups (q16), 32 k each ----
            {
                const float* W2 = dw2 + l * FFD * DIM;
                const float4* Wp = (const float4*)(W2 + (q16 * 32) * DIM) + c;
                const float* xp = sf + q16 * 32;
                float a[4] = {};
#pragma unroll
                for (int k = 0; k < 32; k++) {
                    float xk = xp[k];
                    float4 w = Wp[k * 32];
                    a[0] += xk * w.x; a[1] += xk * w.y;
                    a[2] += xk * w.z; a[3] += xk * w.w;
                }
                *(float4*)&pb0[q16 * 128 + c * 4] = make_float4(a[0], a[1], a[2], a[3]);
            }
            __syncthreads();
            if (tid < 128) {
                float s = ht[tid] + db2[l * DIM + tid];
#pragma unroll
                for (int qq = 0; qq < 16; qq++) s += pb0[qq * 128 + tid];
                su[tid] = s;
            }
            __syncthreads();
            {
                const float* gb = dln + ((l * 3 + 2) * 2) * DIM;
                float mean = blksum512(su[d], red) * (1.f / 512.f);
                float diff = su[d] - mean;
                float var = blksum512(diff * diff, red) * (1.f / 512.f);
                float rstd = rsqrtf(var + 1e-5f);
                if (q4 == 0) ht[d] = gb[d] * diff * rstd + gb[DIM + d];
                __syncthreads();
            }
        }

        // ---- final pointer logits ----
        {
            float a[4] = {};
            gemv4_part(ht, wqf, c, q16, a);
            *(float4*)&pb0[q16 * 128 + c * 4] = make_float4(a[0], a[1], a[2], a[3]);
        }
        __syncthreads();
        if (tid < 128) {
            float s = 0.f;
#pragma unroll
            for (int qq = 0; qq < 16; qq++) s += pb0[qq * 128 + tid];
            sq[tid] = s;
        }
        __syncthreads();
        if (tid < SEQ) {
            const float4* kp = (const float4*)&Kfin[(b * SEQ + tid) * DIM];
            float s = 0.f;
#pragma unroll
            for (int k = 0; k < 32; k++) {
                float4 kv = kp[k];
                s += sq[4 * k] * kv.x + sq[4 * k + 1] * kv.y
                   + sq[4 * k + 2] * kv.z + sq[4 * k + 3] * kv.w;
            }
            float lg = 10.f * tanhf(s * 0.08838834764831845f);   // 1/sqrt(128)
            slg[tid] = smask[tid] ? -1e9f : lg;
        }
        __syncthreads();
        if (tid == 0) {
            float mx = -1e30f;
            int am = 0;
            for (int n = 0; n < SEQ; n++) if (slg[n] > mx) { mx = slg[n]; am = n; }
            float sm = 0.f;
            for (int n = 0; n < SEQ; n++) sm += expf(slg[n] - mx);
            sslp += -logf(sm);      // logp[argmax] = -log(sum exp(l - max))
            smask[am] = 1;
            scur = am;
            out[b * NNOD + t] = (float)am;
        }
        __syncthreads();
    }
    if (tid == 0) out[BB * NNOD + b] = sslp;
}

// ---------------- host launcher ----------------
extern "C" void kernel_launch(void* const* d_in, const int* in_sizes, int n_in,
                              void* d_out, int out_size)
{
    const float* x          = (const float*)d_in[0];
    const float* w_input    = (const float*)d_in[1];
    const float* b_input    = (const float*)d_in[2];
    const float* start_ph   = (const float*)d_in[3];
    const float* enc_attn_w = (const float*)d_in[4];
    const float* enc_attn_b = (const float*)d_in[5];
    const float* enc_ffn_w1 = (const float*)d_in[6];
    const float* enc_ffn_b1 = (const float*)d_in[7];
    const float* enc_ffn_w2 = (const float*)d_in[8];
    const float* enc_ffn_b2 = (const float*)d_in[9];
    const float* enc_bn     = (const float*)d_in[10];
    const float* dec_self_w = (const float*)d_in[11];
    const float* dec_self_b = (const float*)d_in[12];
    const float* dec_cross_w= (const float*)d_in[13];
    const float* dec_cross_b= (const float*)d_in[14];
    const float* dec_ffn_w1 = (const float*)d_in[15];
    const float* dec_ffn_b1 = (const float*)d_in[16];
    const float* dec_ffn_w2 = (const float*)d_in[17];
    const float* dec_ffn_b2 = (const float*)d_in[18];
    const float* dec_ln     = (const float*)d_in[19];
    const float* wk_dec     = (const float*)d_in[20];
    const float* bk_dec     = (const float*)d_in[21];
    const float* wv_dec     = (const float*)d_in[22];
    const float* bv_dec     = (const float*)d_in[23];
    const float* wq_final   = (const float*)d_in[24];
    const float* wk_final   = (const float*)d_in[25];
    float* out = (float*)d_out;

    float* base = nullptr;
    cudaGetSymbolAddress((void**)&base, g_scratch);
    float* ph    = base;
    float* pt    = base + OFF_T;
    float* pQ    = base + OFF_Q;
    float* pf    = base + OFF_F;
    float* pKatt = base + OFF_KATT;
    float* pVatt = base + OFF_VATT;
    float* pKfin = base + OFF_KFIN;
    float* ppart = base + OFF_PART;
    float* pmean = base + OFF_MEAN;
    float* prstd = base + OFF_RSTD;
    float* ppe   = base + OFF_PE;
    float* pKc   = base + OFF_KC;
    float* pVc   = base + OFF_VC;

    embed_kernel<<<(MTOT * DIM + 255) / 256, 256>>>(x, w_input, b_input, start_ph, ph);
    pe_kernel<<<(NNOD * DIM + 255) / 256, 256>>>(ppe);

    dim3 gDD(DIM / 64, MTOT / 64);            // N=128
    dim3 gQKV(DIM / 64, MTOT / 64, 3);        // fused Q,K,V
    dim3 gDF(FFD / 64, MTOT / 64);            // N=512
    dim3 gD2(256 / 64, MTOT / 64);            // N=256

    for (int l = 0; l < NLE; l++) {
        const float* aw = enc_attn_w + (size_t)l * 4 * DIM * DIM;
        const float* ab = enc_attn_b + (size_t)l * 4 * DIM;
        sgemm<true, false, false, true><<<gQKV, 256>>>(ph, aw, ab, nullptr, pQ, MTOT, DIM, DIM);
        enc_attn<<<BB * NH, 256>>>(pQ, pQ + SZ_MD, pQ + 2 * SZ_MD, base + OFF_O);
        sgemm<true, false, true, false><<<gDD, 256>>>(base + OFF_O, aw + 3 * DIM * DIM,
                 ab + 3 * DIM, ph, pt, MTOT, DIM, DIM);
        bn_partial<<<64, 256>>>(pt, ppart);
        bn_reduce<<<1, 128>>>(ppart, pmean, prstd);
        bn_apply<<<(MTOT * DIM + 255) / 256, 256>>>(pt, pmean, prstd,
                 enc_bn + ((l * 2 + 0) * 2 + 0) * DIM, enc_bn + ((l * 2 + 0) * 2 + 1) * DIM, ph);
        sgemm<true, true, false, false><<<gDF, 256>>>(ph, enc_ffn_w1 + (size_t)l * DIM * FFD,
                 enc_ffn_b1 + (size_t)l * FFD, nullptr, pf, MTOT, FFD, DIM);
        sgemm<true, false, true, false><<<gDD, 256>>>(pf, enc_ffn_w2 + (size_t)l * FFD * DIM,
                 enc_ffn_b2 + (size_t)l * DIM, ph, pt, MTOT, DIM, FFD);
        bn_partial<<<64, 256>>>(pt, ppart);
        bn_reduce<<<1, 128>>>(ppart, pmean, prstd);
        bn_apply<<<(MTOT * DIM + 255) / 256, 256>>>(pt, pmean, prstd,
                 enc_bn + ((l * 2 + 1) * 2 + 0) * DIM, enc_bn + ((l * 2 + 1) * 2 + 1) * DIM, ph);
    }

    sgemm<true,  false, false, false><<<gD2, 256>>>(ph, wk_dec,   bk_dec,  nullptr, pKatt, MTOT, NLD * DIM, DIM);
    sgemm<true,  false, false, false><<<gD2, 256>>>(ph, wv_dec,   bv_dec,  nullptr, pVatt, MTOT, NLD * DIM, DIM);
    sgemm<false, false, false, false><<<gDD, 256>>>(ph, wk_final, nullptr, nullptr, pKfin, MTOT, DIM, DIM);

    decoder_kernel<<<BB, 512>>>(ph, ppe, pKatt, pVatt, pKfin, pKc, pVc,
                                dec_self_w, dec_self_b, dec_cross_w, dec_cross_b,
                                dec_ffn_w1, dec_ffn_b1, dec_ffn_w2, dec_ffn_b2,
                                dec_ln, wq_final, out);
}

// round 9
// speedup vs baseline: 1.3128x; 1.2562x over previous
#include <cuda_runtime.h>
#include <math.h>

#define BB   128
#define NNOD 50
#define SEQ  51
#define DIM  128
#define NH   8
#define DHE  16
#define FFD  512
#define NLE  6
#define NLD  2
#define MTOT (BB*SEQ)            // 6528
#define SZ_MD (MTOT*DIM)         // 835584

// decoder smem cache layout
#define KCPAD 17
#define KCH   (NNOD*KCPAD)       // 850 floats per (l,h)
#define KCSZ  (NLD*NH*KCH)       // 13600 floats
#define KFPAD 129
#define KFSZ  (SEQ*KFPAD)        // 6579 floats
#define DYN_FLOATS (2*KCSZ + KFSZ)
#define DYN_BYTES  (DYN_FLOATS*4)

// ---------------- scratch ----------------
#define OFF_T    (SZ_MD)
#define OFF_Q    (2*SZ_MD)
#define OFF_O    (5*SZ_MD)
#define OFF_F    (6*SZ_MD)
#define OFF_KATT (10*SZ_MD)
#define OFF_VATT (12*SZ_MD)
#define OFF_KFIN (14*SZ_MD)
#define OFF_PART (15*SZ_MD)
#define OFF_MEAN (OFF_PART + 16384)
#define OFF_RSTD (OFF_MEAN + 128)
#define OFF_PE   (OFF_RSTD + 128)
#define SCRATCH_TOTAL (OFF_PE + NNOD*DIM)

__device__ float g_scratch[SCRATCH_TOTAL];

// ---------------- embedding ----------------
__global__ void embed_kernel(const float* __restrict__ x,
                             const float* __restrict__ w_in,
                             const float* __restrict__ b_in,
                             const float* __restrict__ start_ph,
                             float* __restrict__ h)
{
    int i = blockIdx.x * blockDim.x + threadIdx.x;
    if (i >= MTOT * DIM) return;
    int d = i & 127;
    int row = i >> 7;
    int s = row % SEQ;
    int b = row / SEQ;
    float v;
    if (s < NNOD) {
        const float* xp = x + (b * NNOD + s) * 2;
        v = xp[0] * w_in[d] + xp[1] * w_in[DIM + d] + b_in[d];
    } else {
        v = start_ph[d];
    }
    h[i] = v;
}

// ---------------- positional encoding ----------------
__global__ void pe_kernel(float* __restrict__ pe)
{
    int i = blockIdx.x * blockDim.x + threadIdx.x;
    if (i >= NNOD * DIM) return;
    int t = i >> 7, d = i & 127;
    double e = (double)(2 * (d / 2)) / 128.0;
    double ang = (double)t * pow(10000.0, -e);
    pe[i] = (float)(((d & 1) == 0) ? sin(ang) : cos(ang));
}

// ---------------- SGEMM (double-buffered) ----------------
template<bool BIAS, bool RELU, bool RES, bool ZSTRIDE>
__global__ void __launch_bounds__(256) sgemm(const float* __restrict__ A,
                                             const float* __restrict__ W,
                                             const float* __restrict__ bias,
                                             const float* __restrict__ R,
                                             float* __restrict__ C,
                                             int M, int N, int K)
{
    if (ZSTRIDE) {
        int z = blockIdx.z;
        W += (size_t)z * K * N;
        if (BIAS) bias += (size_t)z * N;
        C += (size_t)z * M * N;
    }
    __shared__ float As[2][16][68];
    __shared__ float Bs[2][16][68];
    int bm = blockIdx.y * 64, bn = blockIdx.x * 64;
    int tid = threadIdx.x;
    int tr = tid >> 4, tc = tid & 15;
    int mA = tid >> 2, kkA = (tid & 3) * 4;
    int krB = tid >> 4, ccB = (tid & 15) * 4;
    float acc[4][4] = {};

    {
        float4 av = *(const float4*)&A[(bm + mA) * K + kkA];
        float4 bv = *(const float4*)&W[krB * N + bn + ccB];
        As[0][kkA + 0][mA] = av.x; As[0][kkA + 1][mA] = av.y;
        As[0][kkA + 2][mA] = av.z; As[0][kkA + 3][mA] = av.w;
        Bs[0][krB][ccB + 0] = bv.x; Bs[0][krB][ccB + 1] = bv.y;
        Bs[0][krB][ccB + 2] = bv.z; Bs[0][krB][ccB + 3] = bv.w;
    }
    __syncthreads();

    int buf = 0;
    for (int k0 = 0; k0 < K; k0 += 16) {
        bool more = (k0 + 16) < K;
        float4 av2, bv2;
        if (more) {
            av2 = *(const float4*)&A[(bm + mA) * K + k0 + 16 + kkA];
            bv2 = *(const float4*)&W[(k0 + 16 + krB) * N + bn + ccB];
        }
#pragma unroll
        for (int k2 = 0; k2 < 16; k2++) {
            float ra[4], rb[4];
#pragma unroll
            for (int i = 0; i < 4; i++) { ra[i] = As[buf][k2][tr * 4 + i]; rb[i] = Bs[buf][k2][tc * 4 + i]; }
#pragma unroll
            for (int i = 0; i < 4; i++)
#pragma unroll
                for (int j = 0; j < 4; j++) acc[i][j] += ra[i] * rb[j];
        }
        if (more) {
            As[buf ^ 1][kkA + 0][mA] = av2.x; As[buf ^ 1][kkA + 1][mA] = av2.y;
            As[buf ^ 1][kkA + 2][mA] = av2.z; As[buf ^ 1][kkA + 3][mA] = av2.w;
            Bs[buf ^ 1][krB][ccB + 0] = bv2.x; Bs[buf ^ 1][krB][ccB + 1] = bv2.y;
            Bs[buf ^ 1][krB][ccB + 2] = bv2.z; Bs[buf ^ 1][krB][ccB + 3] = bv2.w;
        }
        __syncthreads();
        buf ^= 1;
    }
#pragma unroll
    for (int i = 0; i < 4; i++) {
        int m = bm + tr * 4 + i;
#pragma unroll
        for (int j = 0; j < 4; j++) {
            int n = bn + tc * 4 + j;
            float v = acc[i][j];
            if (BIAS) v += bias[n];
            if (RELU) v = fmaxf(v, 0.f);
            if (RES)  v += R[m * N + n];
            C[m * N + n] = v;
        }
    }
}

// ---------------- encoder attention (R8) ----------------
__global__ void __launch_bounds__(256) enc_attn(const float* __restrict__ Q,
                                                const float* __restrict__ K,
                                                const float* __restrict__ V,
                                                float* __restrict__ O)
{
    __shared__ float Qs[SEQ][DHE], Ks[SEQ][DHE], Vs[SEQ][DHE];
    __shared__ float P[SEQ][SEQ + 1];
    int bh = blockIdx.x;
    int b = bh / NH, hh = bh % NH;
    int tid = threadIdx.x;
    for (int i = tid; i < SEQ * 4; i += 256) {
        int s = i >> 2, j4 = (i & 3) * 4;
        int g = (b * SEQ + s) * DIM + hh * DHE + j4;
        *(float4*)&Qs[s][j4] = *(const float4*)&Q[g];
        *(float4*)&Ks[s][j4] = *(const float4*)&K[g];
        *(float4*)&Vs[s][j4] = *(const float4*)&V[g];
    }
    __syncthreads();
    for (int p = tid; p < SEQ * SEQ; p += 256) {
        int q = p / SEQ, k = p % SEQ;
        float s = 0.f;
#pragma unroll
        for (int j = 0; j < DHE; j++) s += Qs[q][j] * Ks[k][j];
        P[q][k] = s * 0.25f;
    }
    __syncthreads();
    {
        int w = tid >> 5, lane = tid & 31;
        for (int q = w; q < SEQ; q += 8) {
            float v0 = (lane < SEQ) ? P[q][lane] : -1e30f;
            float v1 = (lane + 32 < SEQ) ? P[q][lane + 32] : -1e30f;
            float mx = fmaxf(v0, v1);
#pragma unroll
            for (int o = 16; o; o >>= 1) mx = fmaxf(mx, __shfl_xor_sync(0xffffffffu, mx, o));
            float e0 = (lane < SEQ) ? expf(v0 - mx) : 0.f;
            float e1 = (lane + 32 < SEQ) ? expf(v1 - mx) : 0.f;
            float sm = e0 + e1;
#pragma unroll
            for (int o = 16; o; o >>= 1) sm += __shfl_xor_sync(0xffffffffu, sm, o);
            float inv = 1.f / sm;
            if (lane < SEQ) P[q][lane] = e0 * inv;
            if (lane + 32 < SEQ) P[q][lane + 32] = e1 * inv;
        }
    }
    __syncthreads();
    for (int p = tid; p < SEQ * DHE; p += 256) {
        int q = p >> 4, j = p & 15;
        float s = 0.f;
        for (int k = 0; k < SEQ; k++) s += P[q][k] * Vs[k][j];
        O[(b * SEQ + q) * DIM + hh * DHE + j] = s;
    }
}

// ---------------- BatchNorm (deterministic 3-stage) ----------------
__global__ void __launch_bounds__(256) bn_partial(const float* __restrict__ X,
                                                  float* __restrict__ part)
{
    int d = threadIdx.x & 127, half = threadIdx.x >> 7;
    int r0 = blockIdx.x * 102;
    float s = 0.f, ss = 0.f;
    for (int r = r0 + half; r < r0 + 102; r += 2) {
        float v = X[r * DIM + d];
        s += v; ss += v * v;
    }
    __shared__ float sh[2][2][128];
    sh[half][0][d] = s; sh[half][1][d] = ss;
    __syncthreads();
    if (!half) {
        part[blockIdx.x * 256 + d]       = s + sh[1][0][d];
        part[blockIdx.x * 256 + 128 + d] = ss + sh[1][1][d];
    }
}

__global__ void bn_reduce(const float* __restrict__ part,
                          float* __restrict__ mean, float* __restrict__ rstd)
{
    int d = threadIdx.x;
    float s = 0.f, ss = 0.f;
    for (int b = 0; b < 64; b++) { s += part[b * 256 + d]; ss += part[b * 256 + 128 + d]; }
    float m = s * (1.f / (float)MTOT);
    float v = ss * (1.f / (float)MTOT) - m * m;
    mean[d] = m;
    rstd[d] = rsqrtf(v + 1e-5f);
}

__global__ void __launch_bounds__(256) bn_apply(const float* __restrict__ X,
                                                const float* __restrict__ mean,
                                                const float* __restrict__ rstd,
                                                const float* __restrict__ gamma,
                                                const float* __restrict__ beta,
                                                float* __restrict__ Y)
{
    int i = blockIdx.x * blockDim.x + threadIdx.x;
    if (i >= MTOT * DIM) return;
    int d = i & 127;
    Y[i] = gamma[d] * (X[i] - mean[d]) * rstd[d] + beta[d];
}

// ---------------- decoder helpers ----------------
// float4 partial of a [128 -> 128] GEMV: 32 col-groups (c) x 16 k-groups (q16), 8 k each.
__device__ __forceinline__ void gemv4_part(const float* __restrict__ x,
                                           const float* __restrict__ W,
                                           int c, int q16, float* acc)
{
    const float4* Wp = (const float4*)(W + (q16 * 8) * DIM) + c;
    const float* xp = x + q16 * 8;
#pragma unroll
    for (int k = 0; k < 8; k++) {
        float xk = xp[k];
        float4 w = Wp[k * 32];
        acc[0] += xk * w.x; acc[1] += xk * w.y;
        acc[2] += xk * w.z; acc[3] += xk * w.w;
    }
}

// fused single-pass layernorm over su[0..127] (each value appears 4x in block sum)
__device__ __forceinline__ void layernorm_fused(const float* __restrict__ su,
                                                float* __restrict__ ht,
                                                const float* __restrict__ gb,
                                                int tid, float* red2)
{
    int d = tid & 127;
    float x = su[d];
    float s = x, s2 = x * x;
#pragma unroll
    for (int o = 16; o; o >>= 1) {
        s  += __shfl_down_sync(0xffffffffu, s, o);
        s2 += __shfl_down_sync(0xffffffffu, s2, o);
    }
    int w = tid >> 5;
    if ((tid & 31) == 0) { red2[w] = s; red2[16 + w] = s2; }
    __syncthreads();
    float S = 0.f, S2 = 0.f;
#pragma unroll
    for (int i = 0; i < 16; i++) { S += red2[i]; S2 += red2[16 + i]; }
    float mean = S * (1.f / 512.f);
    float var = S2 * (1.f / 512.f) - mean * mean;
    float rstd = rsqrtf(var + 1e-5f);
    if (tid < 128) ht[d] = gb[d] * (x - mean) * rstd + gb[DIM + d];
    __syncthreads();
}

// ---------------- persistent decoder: 1 batch element per block, 512 threads ----------------
// KV caches + final pointer keys live in (dynamic) shared memory.
__global__ void __launch_bounds__(512) decoder_kernel(
    const float* __restrict__ h_enc, const float* __restrict__ pe,
    const float* __restrict__ Katt, const float* __restrict__ Vatt,
    const float* __restrict__ Kfin,
    const float* __restrict__ dsw, const float* __restrict__ dsb,
    const float* __restrict__ dcw, const float* __restrict__ dcb,
    const float* __restrict__ dw1, const float* __restrict__ db1,
    const float* __restrict__ dw2, const float* __restrict__ db2,
    const float* __restrict__ dln, const float* __restrict__ wqf,
    float* __restrict__ out)
{
    extern __shared__ float dsm[];
    float* sKc   = dsm;                    // [NLD*NH][NNOD*KCPAD]
    float* sVc   = dsm + KCSZ;
    float* sKfin = dsm + 2 * KCSZ;         // [SEQ][KFPAD]

    int tid = threadIdx.x;
    int b = blockIdx.x;
    int d = tid & 127;
    int q4 = tid >> 7;
    int c = tid & 31;
    int q16 = tid >> 5;
    int hh = d >> 4, dh = d & 15;
    int wid = tid >> 5, lane = tid & 31;

    __shared__ float ht[DIM], sq[DIM], so[DIM], su[DIM];
    __shared__ float sf[FFD];
    __shared__ float pb0[2048], pb1[2048], pb2[2048];
    __shared__ float sc[NH][SEQ + 1];
    __shared__ float red2[32];
    __shared__ float slg[SEQ];
    __shared__ int   smask[SEQ];
    __shared__ int   scur;
    __shared__ float sslp;

    // preload final pointer keys into smem (padded rows, conflict-free later)
    for (int i = tid; i < SEQ * DIM; i += 512) {
        int r = i >> 7, cc = i & 127;
        sKfin[r * KFPAD + cc] = Kfin[(b * SEQ + r) * DIM + cc];
    }
    if (tid < SEQ) smask[tid] = (tid == NNOD) ? 1 : 0;
    if (tid == 0) { scur = NNOD; sslp = 0.f; }
    __syncthreads();

    for (int t = 0; t < NNOD; t++) {
        if (q4 == 0) ht[d] = h_enc[(b * SEQ + scur) * DIM + d] + pe[t * DIM + d];
        __syncthreads();

        for (int l = 0; l < NLD; l++) {
            const float* W  = dsw + l * 4 * DIM * DIM;
            const float* bb = dsb + l * 4 * DIM;

            // ---- QKV: three simultaneous float4 split-K partials ----
            {
                float aq[4] = {}, ak[4] = {}, av[4] = {};
                gemv4_part(ht, W,                 c, q16, aq);
                gemv4_part(ht, W + DIM * DIM,     c, q16, ak);
                gemv4_part(ht, W + 2 * DIM * DIM, c, q16, av);
                *(float4*)&pb0[q16 * 128 + c * 4] = make_float4(aq[0], aq[1], aq[2], aq[3]);
                *(float4*)&pb1[q16 * 128 + c * 4] = make_float4(ak[0], ak[1], ak[2], ak[3]);
                *(float4*)&pb2[q16 * 128 + c * 4] = make_float4(av[0], av[1], av[2], av[3]);
            }
            __syncthreads();
            {
                if (tid < 128) {
                    float s = bb[tid];
#pragma unroll
                    for (int qq = 0; qq < 16; qq++) s += pb0[qq * 128 + tid];
                    sq[tid] = s;
                } else if (tid < 256) {
                    int dd = tid - 128;
                    float s = bb[DIM + dd];
#pragma unroll
                    for (int qq = 0; qq < 16; qq++) s += pb1[qq * 128 + dd];
                    sKc[(l * NH + (dd >> 4)) * KCH + t * KCPAD + (dd & 15)] = s;
                } else if (tid < 384) {
                    int dd = tid - 256;
                    float s = bb[2 * DIM + dd];
#pragma unroll
                    for (int qq = 0; qq < 16; qq++) s += pb2[qq * 128 + dd];
                    sVc[(l * NH + (dd >> 4)) * KCH + t * KCPAD + (dd & 15)] = s;
                }
            }
            __syncthreads();

            // ---- self-attn scores (Kc in smem) ----
            int nt = t + 1;
            if (tid < NH * nt) {
                int ph = tid / nt, ps = tid % nt;
                const float* kp = &sKc[(l * NH + ph) * KCH + ps * KCPAD];
                const float* qp = &sq[ph * DHE];
                float s = 0.f;
#pragma unroll
                for (int j = 0; j < DHE; j++) s += qp[j] * kp[j];
                sc[ph][ps] = s * 0.25f;
            }
            __syncthreads();
            // ---- warp-parallel softmax: warp h handles head h ----
            if (wid < NH) {
                float v0 = (lane < nt) ? sc[wid][lane] : -1e30f;
                float v1 = (lane + 32 < nt) ? sc[wid][lane + 32] : -1e30f;
                float mx = fmaxf(v0, v1);
#pragma unroll
                for (int o = 16; o; o >>= 1) mx = fmaxf(mx, __shfl_xor_sync(0xffffffffu, mx, o));
                float e0 = (lane < nt) ? expf(v0 - mx) : 0.f;
                float e1 = (lane + 32 < nt) ? expf(v1 - mx) : 0.f;
                float sm = e0 + e1;
#pragma unroll
                for (int o = 16; o; o >>= 1) sm += __shfl_xor_sync(0xffffffffu, sm, o);
                float inv = 1.f / sm;
                if (lane < nt) sc[wid][lane] = e0 * inv;
                if (lane + 32 < nt) sc[wid][lane + 32] = e1 * inv;
            }
            __syncthreads();
            // ---- V-weighted sum (Vc in smem), s-range split across q4 ----
            {
                int s0 = (nt * q4) >> 2, s1 = (nt * (q4 + 1)) >> 2;
                const float* vp = &sVc[(l * NH + hh) * KCH + dh];
                float oo = 0.f;
#pragma unroll 4
                for (int s = s0; s < s1; s++) oo += sc[hh][s] * vp[s * KCPAD];
                pb0[q4 * 128 + d] = oo;
            }
            __syncthreads();
            if (tid < 128) so[tid] = pb0[tid] + pb0[128 + tid] + pb0[256 + tid] + pb0[384 + tid];
            __syncthreads();
            // ---- Wo + residual ----
            {
                float a[4] = {};
                gemv4_part(so, W + 3 * DIM * DIM, c, q16, a);
                *(float4*)&pb0[q16 * 128 + c * 4] = make_float4(a[0], a[1], a[2], a[3]);
            }
            __syncthreads();
            if (tid < 128) {
                float s = ht[tid] + bb[3 * DIM + tid];
#pragma unroll
                for (int qq = 0; qq < 16; qq++) s += pb0[qq * 128 + tid];
                su[tid] = s;
            }
            __syncthreads();
            layernorm_fused(su, ht, dln + ((l * 3 + 0) * 2) * DIM, tid, red2);

            // ---- cross attention ----
            const float* Wc = dcw + l * 2 * DIM * DIM;
            const float* bc = dcb + l * 2 * DIM;
            {
                float a[4] = {};
                gemv4_part(ht, Wc, c, q16, a);
                *(float4*)&pb0[q16 * 128 + c * 4] = make_float4(a[0], a[1], a[2], a[3]);
            }
            __syncthreads();
            if (tid < 128) {
                float s = bc[tid];
#pragma unroll
                for (int qq = 0; qq < 16; qq++) s += pb0[qq * 128 + tid];
                sq[tid] = s;
            }
            __syncthreads();
            if (tid < NH * SEQ) {
                int ph = tid / SEQ, pn = tid % SEQ;
                const float* kp = &Katt[(b * SEQ + pn) * (NLD * DIM) + l * DIM + ph * DHE];
                const float* qp = &sq[ph * DHE];
                float s = 0.f;
#pragma unroll
                for (int j = 0; j < DHE; j++) s += qp[j] * kp[j];
                sc[ph][pn] = s * 0.25f;
            }
            __syncthreads();
            if (wid < NH) {
                float v0 = (lane < SEQ) ? sc[wid][lane] : -1e30f;
                float v1 = (lane + 32 < SEQ) ? sc[wid][lane + 32] : -1e30f;
                float mx = fmaxf(v0, v1);
#pragma unroll
                for (int o = 16; o; o >>= 1) mx = fmaxf(mx, __shfl_xor_sync(0xffffffffu, mx, o));
                float e0 = (lane < SEQ) ? expf(v0 - mx) : 0.f;
                float e1 = (lane + 32 < SEQ) ? expf(v1 - mx) : 0.f;
                float sm = e0 + e1;
#pragma unroll
                for (int o = 16; o; o >>= 1) sm += __shfl_xor_sync(0xffffffffu, sm, o);
                float inv = 1.f / sm;
                if (lane < SEQ) sc[wid][lane] = e0 * inv;
                if (lane + 32 < SEQ) sc[wid][lane + 32] = e1 * inv;
            }
            __syncthreads();
            {
                int s0 = (SEQ * q4) >> 2, s1 = (SEQ * (q4 + 1)) >> 2;
                const float* vp = &Vatt[b * SEQ * (NLD * DIM) + l * DIM + d];
                float oo = 0.f;
#pragma unroll 4
                for (int n = s0; n < s1; n++) oo += sc[hh][n] * vp[n * NLD * DIM];
                pb0[q4 * 128 + d] = oo;
            }
            __syncthreads();
            if (tid < 128) so[tid] = pb0[tid] + pb0[128 + tid] + pb0[256 + tid] + pb0[384 + tid];
            __syncthreads();
            {
                float a[4] = {};
                gemv4_part(so, Wc + DIM * DIM, c, q16, a);
                *(float4*)&pb0[q16 * 128 + c * 4] = make_float4(a[0], a[1], a[2], a[3]);
            }
            __syncthreads();
            if (tid < 128) {
                float s = ht[tid] + bc[DIM + tid];
#pragma unroll
                for (int qq = 0; qq < 16; qq++) s += pb0[qq * 128 + tid];
                su[tid] = s;
            }
            __syncthreads();
            layernorm_fused(su, ht, dln + ((l * 3 + 1) * 2) * DIM, tid, red2);

            // ---- FFN1 ----
            {
                int cc = tid & 127;
                const float* W1 = dw1 + l * DIM * FFD;
                const float4* Wp = (const float4*)(W1 + (q4 * 32) * FFD) + cc;
                const float* xp = ht + q4 * 32;
                float a[4] = {};
#pragma unroll
                for (int k = 0; k < 32; k++) {
                    float xk = xp[k];
                    float4 w = Wp[k * 128];
                    a[0] += xk * w.x; a[1] += xk * w.y;
                    a[2] += xk * w.z; a[3] += xk * w.w;
                }
                *(float4*)&pb0[q4 * 512 + cc * 4] = make_float4(a[0], a[1], a[2], a[3]);
            }
            __syncthreads();
            sf[tid] = fmaxf(db1[l * FFD + tid] + pb0[tid] + pb0[512 + tid]
                            + pb0[1024 + tid] + pb0[1536 + tid], 0.f);
            __syncthreads();
            // ---- FFN2 ----
            {
                const float* W2 = dw2 + l * FFD * DIM;
                const float4* Wp = (const float4*)(W2 + (q16 * 32) * DIM) + c;
                const float* xp = sf + q16 * 32;
                float a[4] = {};
#pragma unroll
                for (int k = 0; k < 32; k++) {
                    float xk = xp[k];
                    float4 w = Wp[k * 32];
                    a[0] += xk * w.x; a[1] += xk * w.y;
                    a[2] += xk * w.z; a[3] += xk * w.w;
                }
                *(float4*)&pb0[q16 * 128 + c * 4] = make_float4(a[0], a[1], a[2], a[3]);
            }
            __syncthreads();
            if (tid < 128) {
                float s = ht[tid] + db2[l * DIM + tid];
#pragma unroll
                for (int qq = 0; qq < 16; qq++) s += pb0[qq * 128 + tid];
                su[tid] = s;
            }
            __syncthreads();
            layernorm_fused(su, ht, dln + ((l * 3 + 2) * 2) * DIM, tid, red2);
        }

        // ---- final pointer logits (Kfin in smem) ----
        {
            float a[4] = {};
            gemv4_part(ht, wqf, c, q16, a);
            *(float4*)&pb0[q16 * 128 + c * 4] = make_float4(a[0], a[1], a[2], a[3]);
        }
        __syncthreads();
        if (tid < 128) {
            float s = 0.f;
#pragma unroll
            for (int qq = 0; qq < 16; qq++) s += pb0[qq * 128 + tid];
            sq[tid] = s;
        }
        __syncthreads();
        if (tid < SEQ) {
            const float* kp = &sKfin[tid * KFPAD];
            float a0 = 0.f, a1 = 0.f, a2 = 0.f, a3 = 0.f;
#pragma unroll
            for (int k = 0; k < 128; k += 4) {
                a0 += sq[k] * kp[k];
                a1 += sq[k + 1] * kp[k + 1];
                a2 += sq[k + 2] * kp[k + 2];
                a3 += sq[k + 3] * kp[k + 3];
            }
            float s = (a0 + a1) + (a2 + a3);
            float lg = 10.f * tanhf(s * 0.08838834764831845f);   // 1/sqrt(128)
            slg[tid] = smask[tid] ? -1e9f : lg;
        }
        __syncthreads();
        // ---- warp-parallel argmax + logsumexp (warp 0) ----
        if (tid < 32) {
            float v0 = (tid < SEQ) ? slg[tid] : -2e30f; int i0 = tid;
            float v1 = (tid + 32 < SEQ) ? slg[tid + 32] : -2e30f;
            if (v1 > v0) { v0 = v1; i0 = tid + 32; }
#pragma unroll
            for (int o = 16; o; o >>= 1) {
                float vo = __shfl_xor_sync(0xffffffffu, v0, o);
                int io = __shfl_xor_sync(0xffffffffu, i0, o);
                if (vo > v0 || (vo == v0 && io < i0)) { v0 = vo; i0 = io; }
            }
            // v0 = max, i0 = argmax (first occurrence)
            float e0 = (tid < SEQ) ? expf(slg[tid] - v0) : 0.f;
            float e1 = (tid + 32 < SEQ) ? expf(slg[tid + 32] - v0) : 0.f;
            float sm = e0 + e1;
#pragma unroll
            for (int o = 16; o; o >>= 1) sm += __shfl_xor_sync(0xffffffffu, sm, o);
            if (tid == 0) {
                sslp += -logf(sm);
                smask[i0] = 1;
                scur = i0;
                out[b * NNOD + t] = (float)i0;
            }
        }
        __syncthreads();
    }
    if (tid == 0) out[BB * NNOD + b] = sslp;
}

// ---------------- host launcher ----------------
extern "C" void kernel_launch(void* const* d_in, const int* in_sizes, int n_in,
                              void* d_out, int out_size)
{
    const float* x          = (const float*)d_in[0];
    const float* w_input    = (const float*)d_in[1];
    const float* b_input    = (const float*)d_in[2];
    const float* start_ph   = (const float*)d_in[3];
    const float* enc_attn_w = (const float*)d_in[4];
    const float* enc_attn_b = (const float*)d_in[5];
    const float* enc_ffn_w1 = (const float*)d_in[6];
    const float* enc_ffn_b1 = (const float*)d_in[7];
    const float* enc_ffn_w2 = (const float*)d_in[8];
    const float* enc_ffn_b2 = (const float*)d_in[9];
    const float* enc_bn     = (const float*)d_in[10];
    const float* dec_self_w = (const float*)d_in[11];
    const float* dec_self_b = (const float*)d_in[12];
    const float* dec_cross_w= (const float*)d_in[13];
    const float* dec_cross_b= (const float*)d_in[14];
    const float* dec_ffn_w1 = (const float*)d_in[15];
    const float* dec_ffn_b1 = (const float*)d_in[16];
    const float* dec_ffn_w2 = (const float*)d_in[17];
    const float* dec_ffn_b2 = (const float*)d_in[18];
    const float* dec_ln     = (const float*)d_in[19];
    const float* wk_dec     = (const float*)d_in[20];
    const float* bk_dec     = (const float*)d_in[21];
    const float* wv_dec     = (const float*)d_in[22];
    const float* bv_dec     = (const float*)d_in[23];
    const float* wq_final   = (const float*)d_in[24];
    const float* wk_final   = (const float*)d_in[25];
    float* out = (float*)d_out;

    float* base = nullptr;
    cudaGetSymbolAddress((void**)&base, g_scratch);
    float* ph    = base;
    float* pt    = base + OFF_T;
    float* pQ    = base + OFF_Q;
    float* pf    = base + OFF_F;
    float* pKatt = base + OFF_KATT;
    float* pVatt = base + OFF_VATT;
    float* pKfin = base + OFF_KFIN;
    float* ppart = base + OFF_PART;
    float* pmean = base + OFF_MEAN;
    float* prstd = base + OFF_RSTD;
    float* ppe   = base + OFF_PE;

    // decoder needs > 48KB dynamic smem
    cudaFuncSetAttribute(decoder_kernel, cudaFuncAttributeMaxDynamicSharedMemorySize, DYN_BYTES);

    embed_kernel<<<(MTOT * DIM + 255) / 256, 256>>>(x, w_input, b_input, start_ph, ph);
    pe_kernel<<<(NNOD * DIM + 255) / 256, 256>>>(ppe);

    dim3 gDD(DIM / 64, MTOT / 64);
    dim3 gQKV(DIM / 64, MTOT / 64, 3);
    dim3 gDF(FFD / 64, MTOT / 64);
    dim3 gD2(256 / 64, MTOT / 64);

    for (int l = 0; l < NLE; l++) {
        const float* aw = enc_attn_w + (size_t)l * 4 * DIM * DIM;
        const float* ab = enc_attn_b + (size_t)l * 4 * DIM;
        sgemm<true, false, false, true><<<gQKV, 256>>>(ph, aw, ab, nullptr, pQ, MTOT, DIM, DIM);
        enc_attn<<<BB * NH, 256>>>(pQ, pQ + SZ_MD, pQ + 2 * SZ_MD, base + OFF_O);
        sgemm<true, false, true, false><<<gDD, 256>>>(base + OFF_O, aw + 3 * DIM * DIM,
                 ab + 3 * DIM, ph, pt, MTOT, DIM, DIM);
        bn_partial<<<64, 256>>>(pt, ppart);
        bn_reduce<<<1, 128>>>(ppart, pmean, prstd);
        bn_apply<<<(MTOT * DIM + 255) / 256, 256>>>(pt, pmean, prstd,
                 enc_bn + ((l * 2 + 0) * 2 + 0) * DIM, enc_bn + ((l * 2 + 0) * 2 + 1) * DIM, ph);
        sgemm<true, true, false, false><<<gDF, 256>>>(ph, enc_ffn_w1 + (size_t)l * DIM * FFD,
                 enc_ffn_b1 + (size_t)l * FFD, nullptr, pf, MTOT, FFD, DIM);
        sgemm<true, false, true, false><<<gDD, 256>>>(pf, enc_ffn_w2 + (size_t)l * FFD * DIM,
                 enc_ffn_b2 + (size_t)l * DIM, ph, pt, MTOT, DIM, FFD);
        bn_partial<<<64, 256>>>(pt, ppart);
        bn_reduce<<<1, 128>>>(ppart, pmean, prstd);
        bn_apply<<<(MTOT * DIM + 255) / 256, 256>>>(pt, pmean, prstd,
                 enc_bn + ((l * 2 + 1) * 2 + 0) * DIM, enc_bn + ((l * 2 + 1) * 2 + 1) * DIM, ph);
    }

    sgemm<true,  false, false, false><<<gD2, 256>>>(ph, wk_dec,   bk_dec,  nullptr, pKatt, MTOT, NLD * DIM, DIM);
    sgemm<true,  false, false, false><<<gD2, 256>>>(ph, wv_dec,   bv_dec,  nullptr, pVatt, MTOT, NLD * DIM, DIM);
    sgemm<false, false, false, false><<<gDD, 256>>>(ph, wk_final, nullptr, nullptr, pKfin, MTOT, DIM, DIM);

    decoder_kernel<<<BB, 512, DYN_BYTES>>>(ph, ppe, pKatt, pVatt, pKfin,
                                dec_self_w, dec_self_b, dec_cross_w, dec_cross_b,
                                dec_ffn_w1, dec_ffn_b1, dec_ffn_w2, dec_ffn_b2,
                                dec_ln, wq_final, out);
}